// round 7
// baseline (speedup 1.0000x reference)
#include <cuda_runtime.h>
#include <cstdint>

// SlidingWindowCmn (16, 60000, 80) fp32, window=600, min=100, center=False,
// norm_vars=True.
// Distributed 16B cp.async -> 704-row SMEM ring (+8 mirror) -> TWO row-phase
// threads per feature (160 threads): phase r emits rows == r (mod 2),
// recurrence steps by 2 (add x[t-1],x[t]; sub x[t-602],x[t-601]).
// 16-row groups, wait_group 4 + __syncthreads per group, lead = 5 groups
// (cross-thread overwrite safety: lead*16 <= (704-601)-15 = 88).

namespace {
constexpr int kB      = 16;
constexpr int kT      = 60000;
constexpr int kF      = 80;
constexpr int kWin    = 600;
constexpr int kMin    = 100;
constexpr int kChunks = 9;
constexpr int kL      = 6672;                 // 8*6672 + 6624 = 60000
constexpr int kRL     = 704;                  // logical ring rows
constexpr int kRLf    = kRL * kF;             // 56320 floats
constexpr uint32_t kRLb = kRL * 320u;         // 225280 bytes (logical)
constexpr int kScr    = 320;                  // scratch floats (in front)
constexpr uint32_t kSmemB = kScr * 4u + (kRL + 8) * 320u;  // 229120 B
constexpr int kVO     = kRL - kWin - 1;       // 103 rows vn->vo distance
constexpr float kInvW = 1.0f / 601.0f;
constexpr int kGrid   = kB * kChunks;         // 144
constexpr int kThr    = 160;                  // 2 phases x 80 features
}

__device__ __forceinline__ uint32_t smem_u32(const void* p) {
    uint32_t a;
    asm("{ .reg .u64 t; cvta.to.shared.u64 t, %1; cvt.u32.u64 %0, t; }"
        : "=r"(a) : "l"(p));
    return a;
}
__device__ __forceinline__ void cpa16(uint32_t s, const float* g) {
    asm volatile("cp.async.cg.shared.global [%0], [%1], 16;" :: "r"(s), "l"(g));
}
__device__ __forceinline__ void cpcommit() {
    asm volatile("cp.async.commit_group;" ::: "memory");
}
__device__ __forceinline__ void cpwait4() {
    asm volatile("cp.async.wait_group 4;" ::: "memory");
}

__global__ void __launch_bounds__(kThr, 1)
cmn_kernel(const float* __restrict__ x, float* __restrict__ out)
{
    extern __shared__ float smem[];
    float* scratch = smem;                    // 320 floats; also absorbs the
    float* ring    = smem + kScr;             // never-used ring[-80..-1] reads

    const int tid = threadIdx.x;
    const int r   = tid / 80;                 // row phase 0/1
    const int f   = tid - r * 80;             // feature 0..79
    const int c   = blockIdx.x % kChunks;
    const int b   = blockIdx.x / kChunks;

    const float* xb = x + (size_t)b * kT * kF;
    const int start = c * kL;
    const int end   = (c == kChunks - 1) ? kT : start + kL;

    const uint32_t rsb = smem_u32(ring);
    const float* pClamp = x + ((size_t)kB * kT - 16) * kF;

    int vnF;                  // consume group float-offset (slot*80)
    uint32_t issB;            // issue group byte-offset
    const float* pIss;
    if (c == 0) {
        vnF = 0; issB = 0; pIss = xb;
    } else {
        const int t0   = start - 608;         // 16-aligned: 7 pad + 601 warmup
        const int slot = t0 % kRL;
        vnF = slot * kF; issB = (uint32_t)slot * 320u;
        pIss = xb + (size_t)t0 * kF;
    }

    auto issue16 = [&]() {
        const float* q  = (pIss > pClamp) ? pClamp : pIss;
        const float* qt = q + tid * 8;                      // 32 B per thread
        const uint32_t a = rsb + issB + (uint32_t)tid * 32u;
        cpa16(a, qt);
        cpa16(a + 16u, qt + 4);
        if (issB == 0)                                       // mirror rows 0..7
            cpa16(rsb + kRLb + (uint32_t)tid * 16u, q + tid * 4);
        cpcommit();
        pIss += 16 * kF;
        issB += 5120u; if (issB == kRLb) issB = 0;
    };

    #pragma unroll 1
    for (int g = 0; g < 5; ++g) issue16();    // prologue: 5 groups in flight

    float mean = 0.f, qss = 0.f;
    float* po = out + (size_t)b * kT * kF + f;
    int nSteady, g0row;

    if (c == 0) {
        // ---- boundary [0, 608) solo on phase 0; phase 1 idles in step ----
        float s = 0.f, ss = 0.f;
        #pragma unroll 1
        for (int g = 0; g < 6; ++g) {                       // rows 0..95
            cpwait4(); __syncthreads();
            if (r == 0) {
                const float* rv = ring + vnF + f;
                #pragma unroll
                for (int u = 0; u < 16; ++u) {
                    float v = rv[u * kF]; s += v; ss = __fmaf_rn(v, v, ss);
                }
            }
            vnF += 16 * kF; issue16();
        }
        {                                                   // rows 96..111
            cpwait4(); __syncthreads();
            if (r == 0) {
                const float* rv = ring + vnF + f;
                #pragma unroll
                for (int u = 0; u < 4; ++u) {               // 96..99
                    float v = rv[u * kF]; s += v; ss = __fmaf_rn(v, v, ss);
                }
                const float inv = 1.0f / (float)kMin;       // burst rows 0..99
                const float m   = s * inv;
                const float var = __fmaf_rn(-m, m, ss * inv);
                const float rs  = rsqrtf(var);
                #pragma unroll 4
                for (int t = 0; t < kMin; ++t) {
                    float v = ring[t * kF + f];
                    __stcs(po + t * kF, (v - m) * rs);
                }
                float n = 100.0f;
                #pragma unroll
                for (int u = 4; u < 16; ++u) {              // 100..111 growing
                    float v = rv[u * kF]; s += v; ss = __fmaf_rn(v, v, ss);
                    n += 1.0f;
                    float inv2 = __fdividef(1.0f, n);
                    float m2   = s * inv2;
                    float var2 = __fmaf_rn(-m2, m2, ss * inv2);
                    __stcs(po + (96 + u) * kF, (v - m2) * rsqrtf(var2));
                }
            }
            vnF += 16 * kF; issue16();
        }
        float n2 = 112.0f;
        float* pob = po + 112 * kF;
        #pragma unroll 1
        for (int g = 7; g < 37; ++g) {                      // rows 112..591
            cpwait4(); __syncthreads();
            if (r == 0) {
                const float* rv = ring + vnF + f;
                #pragma unroll
                for (int u = 0; u < 16; ++u) {
                    float v = rv[u * kF]; s += v; ss = __fmaf_rn(v, v, ss);
                    n2 += 1.0f;
                    float inv = __fdividef(1.0f, n2);
                    float m   = s * inv;
                    float var = __fmaf_rn(-m, m, ss * inv);
                    __stcs(pob + u * kF, (v - m) * rsqrtf(var));
                }
                pob += 16 * kF;
            }
            vnF += 16 * kF; issue16();
        }
        {                                                   // rows 592..607
            cpwait4(); __syncthreads();
            if (r == 0) {
                const float* rv = ring + vnF + f;
                #pragma unroll
                for (int u = 0; u < 8; ++u) {               // 592..599 growing
                    float v = rv[u * kF]; s += v; ss = __fmaf_rn(v, v, ss);
                    n2 += 1.0f;
                    float inv = __fdividef(1.0f, n2);
                    float m   = s * inv;
                    float var = __fmaf_rn(-m, m, ss * inv);
                    __stcs(pob + u * kF, (v - m) * rsqrtf(var));
                }
                mean = s * kInvW; qss = ss * kInvW;
                #pragma unroll
                for (int u = 8; u < 16; ++u) {              // 600..607 steady-1
                    float vn = rv[u * kF];
                    float vo = (u == 8) ? 0.0f : ring[(u - 9) * kF + f];
                    float t1 = (vn - vo) * kInvW;
                    mean += t1;
                    qss   = __fmaf_rn(t1, vn + vo, qss);
                    float var = __fmaf_rn(-mean, mean, qss);
                    __stcs(pob + u * kF, (vn - mean) * rsqrtf(var));
                }
            }
            vnF += 16 * kF; issue16();
        }
        // ---- handoff: phase 1 gets window state [7, 607] ----
        if (r == 0) { scratch[f] = mean; scratch[80 + f] = qss; }
        __syncthreads();
        if (r == 1) { mean = scratch[f]; qss = scratch[80 + f]; }
        // phase 0 shifts to prev-window [6, 606]: remove x[607], add x[6]
        if (r == 0) {
            float v1 = ring[607 * kF + f], v0 = ring[6 * kF + f];
            mean = __fmaf_rn(v0 - v1, kInvW, mean);
            qss  = __fmaf_rn(v0 * v0 - v1 * v1, kInvW, qss);
        }
        g0row   = 608;
        nSteady = (kL - 608) / 16;                          // 379
    } else {
        // ---- warmup rows [start-601, start): parity-split + combine ----
        float s = 0.f, ss = 0.f;
        {                                                   // partial group
            cpwait4(); __syncthreads();
            const float* pv = ring + vnF + r * kF + f;
            #pragma unroll
            for (int k = 0; k < 8; ++k) {
                int u = r + 2 * k;
                if (u >= 7) {                               // rows t0+7..t0+15
                    float v = pv[2 * k * kF];
                    s += v; ss = __fmaf_rn(v, v, ss);
                }
            }
            vnF += 16 * kF; if (vnF == kRLf) vnF = 0;
            issue16();
        }
        #pragma unroll 1
        for (int g = 1; g < 38; ++g) {                      // 592 rows
            cpwait4(); __syncthreads();
            const float* pv = ring + vnF + r * kF + f;
            #pragma unroll
            for (int k = 0; k < 8; ++k) {
                float v = pv[2 * k * kF];
                s += v; ss = __fmaf_rn(v, v, ss);
            }
            vnF += 16 * kF; if (vnF == kRLf) vnF = 0;
            issue16();
        }
        scratch[tid] = s; scratch[160 + tid] = ss;          // combine phases
        __syncthreads();
        const int o = (tid < 80) ? tid + 80 : tid - 80;
        s += scratch[o]; ss += scratch[160 + o];
        __syncthreads();
        mean = s * kInvW; qss = ss * kInvW;                 // window [start-601, start-1]
        if (r == 0) {   // phase0 prev-window [start-602, start-2]
            const int s1 = (start - 1) % kRL, s2 = (start - 602) % kRL;
            float v1 = ring[s1 * kF + f], v0 = ring[s2 * kF + f];
            mean = __fmaf_rn(v0 - v1, kInvW, mean);
            qss  = __fmaf_rn(v0 * v0 - v1 * v1, kInvW, qss);
        }
        g0row   = start;
        nSteady = (end - start) / 16;                       // 417 or 414
    }

    // ---- steady: phase r emits rows g0+r, g0+r+2, ... (8 per group) ----
    float* po2 = out + (size_t)b * kT * kF + (size_t)g0row * kF + r * kF + f;
    #pragma unroll 1
    for (int g = 0; g < nSteady; ++g) {
        cpwait4(); __syncthreads();
        int voF = vnF + kVO * kF; if (voF >= kRLf) voF -= kRLf;
        const float* pvn = ring + vnF + r * kF + f;
        const float* pvo = ring + voF + r * kF + f;
        int pm = vnF + r * kF - kF; if (pm < 0) pm += kRLf; // row (g0+r-1)
        const float vn0f = ring[pm + f];
        #pragma unroll
        for (int k = 0; k < 8; ++k) {
            float vn1 = pvn[2 * k * kF];                    // x[t]
            float vn0 = (k == 0) ? vn0f : pvn[(2 * k - 1) * kF];  // x[t-1]
            float vo1 = pvo[2 * k * kF];                    // x[t-601]
            float vo0 = pvo[(2 * k - 1) * kF];              // x[t-602]
            float a  = (vn1 - vo1) + (vn0 - vo0);
            mean = __fmaf_rn(a, kInvW, mean);
            float bq = __fmaf_rn(vn0, vn0, vn1 * vn1)
                     - __fmaf_rn(vo0, vo0, vo1 * vo1);
            qss = __fmaf_rn(bq, kInvW, qss);
            float var = __fmaf_rn(-mean, mean, qss);
            __stcs(po2 + 2 * k * kF, (vn1 - mean) * rsqrtf(var));
        }
        vnF += 16 * kF; if (vnF == kRLf) vnF = 0;
        po2 += 16 * kF;
        issue16();
    }
}

extern "C" void kernel_launch(void* const* d_in, const int* in_sizes, int n_in,
                              void* d_out, int out_size)
{
    const float* x = (const float*)d_in[0];
    float* o = (float*)d_out;
    (void)in_sizes; (void)n_in; (void)out_size;

    cudaFuncSetAttribute(cmn_kernel,
                         cudaFuncAttributeMaxDynamicSharedMemorySize, (int)kSmemB);
    cmn_kernel<<<kGrid, kThr, kSmemB>>>(x, o);
}